// round 6
// baseline (speedup 1.0000x reference)
#include <cuda_runtime.h>
#include <cstdint>

// GraphAttention: V=500000, D=128, B=4096, T=3, K=64  (rows = 12288)
// One warp per row. Warp compaction of active neighbors (padded to mult of 16,
// dummy id 0 zero-weighted). Neighbor rows gathered via cp.async.bulk (TMA
// bulk copy, 512 B each) into a per-warp 2-stage smem ring, bypassing the
// L1tex wavefront queue that capped the LDG-based kernels at ~57% DRAM.

#define NUM_ROWS  (4096 * 3)
#define KNEIGH    64
#define DDIM      128
#define INV_ATT_SCALE (1.0f / 15.0f)
#define LN_EPS    1e-5f
#define WPB       4
#define THREADS   (WPB * 32)
#define CHUNK     8
#define NSTAGE    2
#define ROW_BYTES 512
#define STAGE_BYTES (CHUNK * ROW_BYTES)

__device__ __forceinline__ float warp_sum(float v) {
    v += __shfl_xor_sync(0xffffffffu, v, 16);
    v += __shfl_xor_sync(0xffffffffu, v, 8);
    v += __shfl_xor_sync(0xffffffffu, v, 4);
    v += __shfl_xor_sync(0xffffffffu, v, 2);
    v += __shfl_xor_sync(0xffffffffu, v, 1);
    return v;
}

__device__ __forceinline__ void mbar_init(uint32_t mbar, uint32_t count) {
    asm volatile("mbarrier.init.shared.b64 [%0], %1;" :: "r"(mbar), "r"(count) : "memory");
}

__device__ __forceinline__ void wait_chunk(uint32_t mbar, uint32_t parity) {
    asm volatile("{\n\t"
                 ".reg .pred p;\n\t"
                 "WAIT%=:\n\t"
                 "mbarrier.try_wait.parity.acquire.cta.shared::cta.b64 p, [%0], %1;\n\t"
                 "@!p bra WAIT%=;\n\t"
                 "}" :: "r"(mbar), "r"(parity) : "memory");
}

// lane 0: expect 4096 bytes on this stage's barrier, then issue 8 x 512B bulk copies
__device__ __forceinline__ void issue_chunk(uint32_t stage_smem, uint32_t mbar,
                                            const int* __restrict__ list, int base,
                                            const float* __restrict__ emb, int lane)
{
    if (lane == 0) {
        asm volatile("mbarrier.arrive.expect_tx.shared.b64 _, [%0], %1;"
                     :: "r"(mbar), "r"((uint32_t)STAGE_BYTES) : "memory");
        #pragma unroll
        for (int j = 0; j < CHUNK; ++j) {
            const int nb = list[base + j];
            const uint64_t src = (uint64_t)(uintptr_t)(emb + (size_t)nb * DDIM);
            asm volatile("cp.async.bulk.shared::cluster.global.mbarrier::complete_tx::bytes "
                         "[%0], [%1], %2, [%3];"
                         :: "r"(stage_smem + j * ROW_BYTES), "l"(src),
                            "r"((uint32_t)ROW_BYTES), "r"(mbar) : "memory");
        }
    }
}

__global__ __launch_bounds__(THREADS)
void graph_attention_kernel(const int*   __restrict__ node_ids,      // [B,3]
                            const int*   __restrict__ neighbor_ids,  // [B,3,K]
                            const int*   __restrict__ neighbor_mask, // [B,3,K]
                            const float* __restrict__ emb,           // [V,D]
                            const float* __restrict__ gamma,         // [D]
                            const float* __restrict__ beta,          // [D]
                            float*       __restrict__ out)           // [B,3,D]
{
    __shared__ __align__(128) unsigned char s_stage[WPB][NSTAGE][STAGE_BYTES]; // 32 KB
    __shared__ int s_act[WPB][KNEIGH];
    __shared__ __align__(8) unsigned long long s_mbar[WPB][NSTAGE];

    const int w    = threadIdx.x >> 5;
    const int lane = threadIdx.x & 31;
    const int row  = blockIdx.x * WPB + w;   // grid sized exactly

    const uint32_t stage0 = (uint32_t)__cvta_generic_to_shared(&s_stage[w][0][0]);
    const uint32_t stage1 = (uint32_t)__cvta_generic_to_shared(&s_stage[w][1][0]);
    const uint32_t mbar0  = (uint32_t)__cvta_generic_to_shared(&s_mbar[w][0]);
    const uint32_t mbar1  = (uint32_t)__cvta_generic_to_shared(&s_mbar[w][1]);

    if (lane == 0) {
        mbar_init(mbar0, 1);
        mbar_init(mbar1, 1);
        asm volatile("fence.proxy.async.shared::cta;" ::: "memory");
    }
    __syncwarp();

    const float4* __restrict__ embv = reinterpret_cast<const float4*>(emb);
    const int nid = node_ids[row];
    const float4 node = embv[(size_t)nid * 32 + lane];

    // ---- warp-level compaction of active neighbors ----
    const int* __restrict__ nids  = neighbor_ids  + (size_t)row * KNEIGH;
    const int* __restrict__ nmask = neighbor_mask + (size_t)row * KNEIGH;

    const int m0  = nmask[lane];
    const int m1  = nmask[lane + 32];
    const int id0 = nids[lane];
    const int id1 = nids[lane + 32];

    const unsigned full = 0xffffffffu;
    const unsigned b0 = __ballot_sync(full, m0 != 0);
    const unsigned b1 = __ballot_sync(full, m1 != 0);
    const int c0  = __popc(b0);
    const int cnt = c0 + __popc(b1);
    const unsigned lt = (1u << lane) - 1u;

    if (m0) s_act[w][__popc(b0 & lt)]      = id0;
    if (m1) s_act[w][c0 + __popc(b1 & lt)] = id1;

    // pad to a multiple of 16 with dummy id 0 (zero-weighted) -> np is even
    const int pad16 = (cnt + 15) & ~15;
    if (lane < pad16 - cnt) s_act[w][cnt + lane] = 0;
    __syncwarp(full);

    const int* __restrict__ list = s_act[w];

    // ---- TMA-fed 2-stage pipeline ----
    float4 acc = make_float4(0.f, 0.f, 0.f, 0.f);
    const int np = pad16 >> 3;   // 0,2,4,6,8

    if (np > 0) {
        issue_chunk(stage0, mbar0, list, 0, emb, lane);
        if (np > 1) issue_chunk(stage1, mbar1, list, CHUNK, emb, lane);

        for (int c = 0; c < np; ++c) {
            const int s = c & 1;
            const uint32_t mb  = s ? mbar1  : mbar0;
            const uint32_t stg = s ? stage1 : stage0;
            const uint32_t parity = (uint32_t)((c >> 1) & 1);

            wait_chunk(mb, parity);

            const float4* srow = reinterpret_cast<const float4*>(&s_stage[w][s][0]);
            float4 n4[CHUNK];
            float  p[CHUNK];
            #pragma unroll
            for (int j = 0; j < CHUNK; ++j)
                n4[j] = srow[j * 32 + lane];
            #pragma unroll
            for (int j = 0; j < CHUNK; ++j)
                p[j] = n4[j].x * node.x + n4[j].y * node.y
                     + n4[j].z * node.z + n4[j].w * node.w;
            #pragma unroll
            for (int j = 0; j < CHUNK; ++j)
                p[j] = warp_sum(p[j]);
            #pragma unroll
            for (int j = 0; j < CHUNK; ++j) {
                const float att = (c * CHUNK + j < cnt) ? p[j] * INV_ATT_SCALE : 0.0f;
                acc.x += att * n4[j].x;
                acc.y += att * n4[j].y;
                acc.z += att * n4[j].z;
                acc.w += att * n4[j].w;
            }

            __syncwarp();                     // all lanes done with stage s
            if (c + 2 < np)
                issue_chunk(stg, mb, list, (c + 2) * CHUNK, emb, lane);
            (void)stg;
        }
    }

    // ---- x = node + att_out, LayerNorm over D=128 ----
    float4 x;
    x.x = node.x + acc.x;
    x.y = node.y + acc.y;
    x.z = node.z + acc.z;
    x.w = node.w + acc.w;

    const float mu = warp_sum(x.x + x.y + x.z + x.w) * (1.0f / DDIM);

    const float dx0 = x.x - mu, dx1 = x.y - mu, dx2 = x.z - mu, dx3 = x.w - mu;
    const float var = warp_sum(dx0*dx0 + dx1*dx1 + dx2*dx2 + dx3*dx3) * (1.0f / DDIM);
    const float r = rsqrtf(var + LN_EPS);

    const float4 g = reinterpret_cast<const float4*>(gamma)[lane];
    const float4 b = reinterpret_cast<const float4*>(beta)[lane];

    float4 o;
    o.x = dx0 * r * g.x + b.x;
    o.y = dx1 * r * g.y + b.y;
    o.z = dx2 * r * g.z + b.z;
    o.w = dx3 * r * g.w + b.w;

    reinterpret_cast<float4*>(out)[(size_t)row * 32 + lane] = o;
}

extern "C" void kernel_launch(void* const* d_in, const int* in_sizes, int n_in,
                              void* d_out, int out_size)
{
    const int*   node_ids      = (const int*)  d_in[0];
    const int*   neighbor_ids  = (const int*)  d_in[1];
    const int*   neighbor_mask = (const int*)  d_in[2];
    const float* emb           = (const float*)d_in[3];
    const float* gamma         = (const float*)d_in[4];
    const float* beta          = (const float*)d_in[5];
    float*       out           = (float*)d_out;

    const int blocks = NUM_ROWS / WPB;       // 3072, exact

    graph_attention_kernel<<<blocks, THREADS>>>(node_ids, neighbor_ids, neighbor_mask,
                                                emb, gamma, beta, out);
}

// round 7
// speedup vs baseline: 1.0970x; 1.0970x over previous
#include <cuda_runtime.h>
#include <cstdint>

// GraphAttention: V=500000, D=128, B=4096, T=3, K=64  (rows = 12288)
// Hybrid dual-path gather: per warp, the first 2 chunks (16 rows) are fetched
// via cp.async.bulk (TMA engine, issued up front into a 2-stage smem ring);
// remaining chunks use the LDG double-buffered pipeline concurrently. The two
// hardware paths queue independently, adding request supply to DRAM.

#define NUM_ROWS  (4096 * 3)
#define KNEIGH    64
#define DDIM      128
#define INV_ATT_SCALE (1.0f / 15.0f)
#define LN_EPS    1e-5f
#define WPB       4
#define THREADS   (WPB * 32)
#define CHUNK     8
#define ROW_BYTES 512
#define STAGE_BYTES (CHUNK * ROW_BYTES)

__device__ __forceinline__ float warp_sum(float v) {
    v += __shfl_xor_sync(0xffffffffu, v, 16);
    v += __shfl_xor_sync(0xffffffffu, v, 8);
    v += __shfl_xor_sync(0xffffffffu, v, 4);
    v += __shfl_xor_sync(0xffffffffu, v, 2);
    v += __shfl_xor_sync(0xffffffffu, v, 1);
    return v;
}

__device__ __forceinline__ void mbar_init(uint32_t mbar, uint32_t count) {
    asm volatile("mbarrier.init.shared.b64 [%0], %1;" :: "r"(mbar), "r"(count) : "memory");
}

__device__ __forceinline__ void wait_parity0(uint32_t mbar) {
    asm volatile("{\n\t"
                 ".reg .pred p;\n\t"
                 "WAIT%=:\n\t"
                 "mbarrier.try_wait.parity.acquire.cta.shared::cta.b64 p, [%0], 0;\n\t"
                 "@!p bra WAIT%=;\n\t"
                 "}" :: "r"(mbar) : "memory");
}

// lane 0: expect 4096B on the barrier, then issue 8 x 512B bulk copies
__device__ __forceinline__ void issue_tma_chunk(uint32_t stage_smem, uint32_t mbar,
                                                const int* __restrict__ list, int base,
                                                const float* __restrict__ emb, int lane)
{
    if (lane == 0) {
        asm volatile("mbarrier.arrive.expect_tx.shared.b64 _, [%0], %1;"
                     :: "r"(mbar), "r"((uint32_t)STAGE_BYTES) : "memory");
        #pragma unroll
        for (int j = 0; j < CHUNK; ++j) {
            const int nb = list[base + j];
            const uint64_t src = (uint64_t)(uintptr_t)(emb + (size_t)nb * DDIM);
            asm volatile("cp.async.bulk.shared::cluster.global.mbarrier::complete_tx::bytes "
                         "[%0], [%1], %2, [%3];"
                         :: "r"(stage_smem + j * ROW_BYTES), "l"(src),
                            "r"((uint32_t)ROW_BYTES), "r"(mbar) : "memory");
        }
    }
}

// LDG: issue CHUNK gathers into a register buffer
__device__ __forceinline__ void load_chunk(float4 (&buf)[CHUNK],
                                           const int* __restrict__ list, int base,
                                           const float4* __restrict__ embv, int lane)
{
    #pragma unroll
    for (int j = 0; j < CHUNK; ++j) {
        const int nb = list[base + j];
        buf[j] = embv[(size_t)nb * 32 + lane];
    }
}

// dot + butterfly reduce + weight-masked accumulate
__device__ __forceinline__ void proc_chunk(const float4 (&buf)[CHUNK],
                                           int base, int cnt,
                                           const float4& node, float4& acc)
{
    float p[CHUNK];
    #pragma unroll
    for (int j = 0; j < CHUNK; ++j)
        p[j] = buf[j].x * node.x + buf[j].y * node.y
             + buf[j].z * node.z + buf[j].w * node.w;
    #pragma unroll
    for (int j = 0; j < CHUNK; ++j)
        p[j] = warp_sum(p[j]);
    #pragma unroll
    for (int j = 0; j < CHUNK; ++j) {
        const float att = (base + j < cnt) ? p[j] * INV_ATT_SCALE : 0.0f;
        acc.x += att * buf[j].x;
        acc.y += att * buf[j].y;
        acc.z += att * buf[j].z;
        acc.w += att * buf[j].w;
    }
}

__global__ __launch_bounds__(THREADS)
void graph_attention_kernel(const int*   __restrict__ node_ids,      // [B,3]
                            const int*   __restrict__ neighbor_ids,  // [B,3,K]
                            const int*   __restrict__ neighbor_mask, // [B,3,K]
                            const float* __restrict__ emb,           // [V,D]
                            const float* __restrict__ gamma,         // [D]
                            const float* __restrict__ beta,          // [D]
                            float*       __restrict__ out)           // [B,3,D]
{
    __shared__ __align__(128) unsigned char s_stage[WPB][2][STAGE_BYTES]; // 32 KB
    __shared__ int s_act[WPB][KNEIGH];
    __shared__ __align__(8) unsigned long long s_mbar[WPB][2];

    const int w    = threadIdx.x >> 5;
    const int lane = threadIdx.x & 31;
    const int row  = blockIdx.x * WPB + w;   // grid sized exactly

    const uint32_t stage0 = (uint32_t)__cvta_generic_to_shared(&s_stage[w][0][0]);
    const uint32_t stage1 = (uint32_t)__cvta_generic_to_shared(&s_stage[w][1][0]);
    const uint32_t mbar0  = (uint32_t)__cvta_generic_to_shared(&s_mbar[w][0]);
    const uint32_t mbar1  = (uint32_t)__cvta_generic_to_shared(&s_mbar[w][1]);

    if (lane == 0) {
        mbar_init(mbar0, 1);
        mbar_init(mbar1, 1);
        asm volatile("fence.proxy.async.shared::cta;" ::: "memory");
    }
    __syncwarp();

    const float4* __restrict__ embv = reinterpret_cast<const float4*>(emb);
    const int nid = node_ids[row];
    const float4 node = embv[(size_t)nid * 32 + lane];

    // ---- warp-level compaction of active neighbors ----
    const int* __restrict__ nids  = neighbor_ids  + (size_t)row * KNEIGH;
    const int* __restrict__ nmask = neighbor_mask + (size_t)row * KNEIGH;

    const int m0  = nmask[lane];
    const int m1  = nmask[lane + 32];
    const int id0 = nids[lane];
    const int id1 = nids[lane + 32];

    const unsigned full = 0xffffffffu;
    const unsigned b0 = __ballot_sync(full, m0 != 0);
    const unsigned b1 = __ballot_sync(full, m1 != 0);
    const int c0  = __popc(b0);
    const int cnt = c0 + __popc(b1);
    const unsigned lt = (1u << lane) - 1u;

    if (m0) s_act[w][__popc(b0 & lt)]      = id0;
    if (m1) s_act[w][c0 + __popc(b1 & lt)] = id1;

    // pad active list to a multiple of 16 with dummy id 0 (zero-weighted)
    const int pad16 = (cnt + 15) & ~15;      // np = pad16/8 is even
    if (lane < pad16 - cnt) s_act[w][cnt + lane] = 0;
    __syncwarp(full);

    const int* __restrict__ list = s_act[w];
    const int np = pad16 >> 3;               // 0,2,4,6,8

    float4 acc = make_float4(0.f, 0.f, 0.f, 0.f);

    if (np > 0) {
        // ---- launch TMA for chunks 0 and 1 immediately (np even => np>=2) ----
        issue_tma_chunk(stage0, mbar0, list, 0,     emb, lane);
        issue_tma_chunk(stage1, mbar1, list, CHUNK, emb, lane);

        // ---- LDG double-buffered pipeline for chunks 2..np-1 (concurrent) ----
        const int nl = np - 2;               // 0,2,4,6
        if (nl > 0) {
            float4 bufA[CHUNK], bufB[CHUNK];
            load_chunk(bufA, list, 2 * CHUNK, embv, lane);
            for (int c = 0; c < nl; c += 2) {
                load_chunk(bufB, list, (c + 3) * CHUNK, embv, lane);
                proc_chunk(bufA, (c + 2) * CHUNK, cnt, node, acc);
                if (c + 2 < nl)
                    load_chunk(bufA, list, (c + 4) * CHUNK, embv, lane);
                proc_chunk(bufB, (c + 3) * CHUNK, cnt, node, acc);
            }
        }

        // ---- consume the TMA chunks (landed during the LDG phase) ----
        #pragma unroll
        for (int s = 0; s < 2; ++s) {
            wait_parity0(s ? mbar1 : mbar0);
            const float4* srow = reinterpret_cast<const float4*>(&s_stage[w][s][0]);
            float4 n4[CHUNK];
            #pragma unroll
            for (int j = 0; j < CHUNK; ++j)
                n4[j] = srow[j * 32 + lane];
            proc_chunk(n4, s * CHUNK, cnt, node, acc);
        }
    }

    // ---- x = node + att_out, LayerNorm over D=128 ----
    float4 x;
    x.x = node.x + acc.x;
    x.y = node.y + acc.y;
    x.z = node.z + acc.z;
    x.w = node.w + acc.w;

    const float mu = warp_sum(x.x + x.y + x.z + x.w) * (1.0f / DDIM);

    const float dx0 = x.x - mu, dx1 = x.y - mu, dx2 = x.z - mu, dx3 = x.w - mu;
    const float var = warp_sum(dx0*dx0 + dx1*dx1 + dx2*dx2 + dx3*dx3) * (1.0f / DDIM);
    const float r = rsqrtf(var + LN_EPS);

    const float4 g = reinterpret_cast<const float4*>(gamma)[lane];
    const float4 b = reinterpret_cast<const float4*>(beta)[lane];

    float4 o;
    o.x = dx0 * r * g.x + b.x;
    o.y = dx1 * r * g.y + b.y;
    o.z = dx2 * r * g.z + b.z;
    o.w = dx3 * r * g.w + b.w;

    reinterpret_cast<float4*>(out)[(size_t)row * 32 + lane] = o;
}

extern "C" void kernel_launch(void* const* d_in, const int* in_sizes, int n_in,
                              void* d_out, int out_size)
{
    const int*   node_ids      = (const int*)  d_in[0];
    const int*   neighbor_ids  = (const int*)  d_in[1];
    const int*   neighbor_mask = (const int*)  d_in[2];
    const float* emb           = (const float*)d_in[3];
    const float* gamma         = (const float*)d_in[4];
    const float* beta          = (const float*)d_in[5];
    float*       out           = (float*)d_out;

    const int blocks = NUM_ROWS / WPB;       // 3072, exact

    graph_attention_kernel<<<blocks, THREADS>>>(node_ids, neighbor_ids, neighbor_mask,
                                                emb, gamma, beta, out);
}

// round 8
// speedup vs baseline: 1.2250x; 1.1166x over previous
#include <cuda_runtime.h>
#include <cstdint>

// GraphAttention: V=500000, D=128, B=4096, T=3, K=64  (rows = 12288)
// R2 structure (best measured: 36.9us, 4.7TB/s = device ceiling for this
// random-512B gather pattern) + pad-to-16 to eliminate the MLP=1 scalar
// remainder loop. Single register buffer, CHUNK=8, 8 warps/block.

#define NUM_ROWS  (4096 * 3)
#define KNEIGH    64
#define DDIM      128
#define INV_ATT_SCALE (1.0f / 15.0f)
#define LN_EPS    1e-5f
#define WPB       8
#define THREADS   (WPB * 32)
#define CHUNK     8

__device__ __forceinline__ float warp_sum(float v) {
    v += __shfl_xor_sync(0xffffffffu, v, 16);
    v += __shfl_xor_sync(0xffffffffu, v, 8);
    v += __shfl_xor_sync(0xffffffffu, v, 4);
    v += __shfl_xor_sync(0xffffffffu, v, 2);
    v += __shfl_xor_sync(0xffffffffu, v, 1);
    return v;
}

__global__ __launch_bounds__(THREADS)
void graph_attention_kernel(const int*   __restrict__ node_ids,      // [B,3]
                            const int*   __restrict__ neighbor_ids,  // [B,3,K]
                            const int*   __restrict__ neighbor_mask, // [B,3,K]
                            const float* __restrict__ emb,           // [V,D]
                            const float* __restrict__ gamma,         // [D]
                            const float* __restrict__ beta,          // [D]
                            float*       __restrict__ out)           // [B,3,D]
{
    __shared__ int s_act[WPB][KNEIGH];

    const int w    = threadIdx.x >> 5;
    const int lane = threadIdx.x & 31;
    const int row  = blockIdx.x * WPB + w;   // grid sized exactly

    const float4* __restrict__ embv = reinterpret_cast<const float4*>(emb);

    const int nid = node_ids[row];
    const float4 node = embv[(size_t)nid * 32 + lane];

    // ---- warp-level compaction of active neighbors ----
    const int* __restrict__ nids  = neighbor_ids  + (size_t)row * KNEIGH;
    const int* __restrict__ nmask = neighbor_mask + (size_t)row * KNEIGH;

    const int m0  = nmask[lane];
    const int m1  = nmask[lane + 32];
    const int id0 = nids[lane];
    const int id1 = nids[lane + 32];

    const unsigned full = 0xffffffffu;
    const unsigned b0 = __ballot_sync(full, m0 != 0);
    const unsigned b1 = __ballot_sync(full, m1 != 0);
    const int c0  = __popc(b0);
    const int cnt = c0 + __popc(b1);
    const unsigned lt = (1u << lane) - 1u;

    if (m0) s_act[w][__popc(b0 & lt)]      = id0;
    if (m1) s_act[w][c0 + __popc(b1 & lt)] = id1;

    // pad active list to a multiple of 16 with dummy id 0 (weight-masked to 0)
    const int pad16 = (cnt + 15) & ~15;      // <= 64
    if (lane < pad16 - cnt) s_act[w][cnt + lane] = 0;
    __syncwarp(full);

    const int* __restrict__ list = s_act[w];
    const int np = pad16 >> 3;               // even: 0,2,4,6,8

    // ---- dense inner loop: 8 batched gathers per chunk, no remainder ----
    float4 acc = make_float4(0.f, 0.f, 0.f, 0.f);

    for (int c = 0; c < np; ++c) {
        const int base = c * CHUNK;

        float4 n4[CHUNK];
        #pragma unroll
        for (int j = 0; j < CHUNK; ++j) {
            const int nb = list[base + j];
            n4[j] = embv[(size_t)nb * 32 + lane];
        }

        float p[CHUNK];
        #pragma unroll
        for (int j = 0; j < CHUNK; ++j)
            p[j] = n4[j].x * node.x + n4[j].y * node.y
                 + n4[j].z * node.z + n4[j].w * node.w;

        #pragma unroll
        for (int j = 0; j < CHUNK; ++j)
            p[j] = warp_sum(p[j]);   // independent butterfly chains interleave

        #pragma unroll
        for (int j = 0; j < CHUNK; ++j) {
            const float att = (base + j < cnt) ? p[j] * INV_ATT_SCALE : 0.0f;
            acc.x += att * n4[j].x;
            acc.y += att * n4[j].y;
            acc.z += att * n4[j].z;
            acc.w += att * n4[j].w;
        }
    }

    // ---- x = node + att_out, LayerNorm over D=128 ----
    float4 x;
    x.x = node.x + acc.x;
    x.y = node.y + acc.y;
    x.z = node.z + acc.z;
    x.w = node.w + acc.w;

    const float mu = warp_sum(x.x + x.y + x.z + x.w) * (1.0f / DDIM);

    const float dx0 = x.x - mu, dx1 = x.y - mu, dx2 = x.z - mu, dx3 = x.w - mu;
    const float var = warp_sum(dx0*dx0 + dx1*dx1 + dx2*dx2 + dx3*dx3) * (1.0f / DDIM);
    const float r = rsqrtf(var + LN_EPS);

    const float4 g = reinterpret_cast<const float4*>(gamma)[lane];
    const float4 b = reinterpret_cast<const float4*>(beta)[lane];

    float4 o;
    o.x = dx0 * r * g.x + b.x;
    o.y = dx1 * r * g.y + b.y;
    o.z = dx2 * r * g.z + b.z;
    o.w = dx3 * r * g.w + b.w;

    reinterpret_cast<float4*>(out)[(size_t)row * 32 + lane] = o;
}

extern "C" void kernel_launch(void* const* d_in, const int* in_sizes, int n_in,
                              void* d_out, int out_size)
{
    const int*   node_ids      = (const int*)  d_in[0];
    const int*   neighbor_ids  = (const int*)  d_in[1];
    const int*   neighbor_mask = (const int*)  d_in[2];
    const float* emb           = (const float*)d_in[3];
    const float* gamma         = (const float*)d_in[4];
    const float* beta          = (const float*)d_in[5];
    float*       out           = (float*)d_out;

    const int blocks = NUM_ROWS / WPB;       // 1536, exact

    graph_attention_kernel<<<blocks, THREADS>>>(node_ids, neighbor_ids, neighbor_mask,
                                                emb, gamma, beta, out);
}

// round 9
// speedup vs baseline: 1.2845x; 1.0486x over previous
#include <cuda_runtime.h>
#include <cstdint>

// GraphAttention: V=500000, D=128, B=4096, T=3, K=64  (rows = 12288)
// R2 structure (measured best; ~4.7TB/s = structural ceiling for random 512B
// gathers) + pad-to-8 (kills MLP=1 remainder with minimal dummy work) +
// streaming cache hints on single-use data (ids/mask in, output out) to keep
// L2 capacity for the emb table.

#define NUM_ROWS  (4096 * 3)
#define KNEIGH    64
#define DDIM      128
#define INV_ATT_SCALE (1.0f / 15.0f)
#define LN_EPS    1e-5f
#define WPB       8
#define THREADS   (WPB * 32)
#define CHUNK     8

__device__ __forceinline__ float warp_sum(float v) {
    v += __shfl_xor_sync(0xffffffffu, v, 16);
    v += __shfl_xor_sync(0xffffffffu, v, 8);
    v += __shfl_xor_sync(0xffffffffu, v, 4);
    v += __shfl_xor_sync(0xffffffffu, v, 2);
    v += __shfl_xor_sync(0xffffffffu, v, 1);
    return v;
}

__global__ __launch_bounds__(THREADS)
void graph_attention_kernel(const int*   __restrict__ node_ids,      // [B,3]
                            const int*   __restrict__ neighbor_ids,  // [B,3,K]
                            const int*   __restrict__ neighbor_mask, // [B,3,K]
                            const float* __restrict__ emb,           // [V,D]
                            const float* __restrict__ gamma,         // [D]
                            const float* __restrict__ beta,          // [D]
                            float*       __restrict__ out)           // [B,3,D]
{
    __shared__ int s_act[WPB][KNEIGH];

    const int w    = threadIdx.x >> 5;
    const int lane = threadIdx.x & 31;
    const int row  = blockIdx.x * WPB + w;   // grid sized exactly

    const float4* __restrict__ embv = reinterpret_cast<const float4*>(emb);

    const int nid = __ldcs(&node_ids[row]);
    const float4 node = embv[(size_t)nid * 32 + lane];

    // ---- warp-level compaction of active neighbors ----
    const int* __restrict__ nids  = neighbor_ids  + (size_t)row * KNEIGH;
    const int* __restrict__ nmask = neighbor_mask + (size_t)row * KNEIGH;

    const int m0  = __ldcs(&nmask[lane]);
    const int m1  = __ldcs(&nmask[lane + 32]);
    const int id0 = __ldcs(&nids[lane]);
    const int id1 = __ldcs(&nids[lane + 32]);

    const unsigned full = 0xffffffffu;
    const unsigned b0 = __ballot_sync(full, m0 != 0);
    const unsigned b1 = __ballot_sync(full, m1 != 0);
    const int c0  = __popc(b0);
    const int cnt = c0 + __popc(b1);
    const unsigned lt = (1u << lane) - 1u;

    if (m0) s_act[w][__popc(b0 & lt)]      = id0;
    if (m1) s_act[w][c0 + __popc(b1 & lt)] = id1;

    // pad active list to a multiple of 8 with dummy id 0 (weight-masked to 0)
    const int pad8 = (cnt + 7) & ~7;         // <= 64
    if (lane < pad8 - cnt) s_act[w][cnt + lane] = 0;
    __syncwarp(full);

    const int* __restrict__ list = s_act[w];
    const int np = pad8 >> 3;                // 0..8

    // ---- dense inner loop: 8 batched gathers per chunk, no remainder ----
    float4 acc = make_float4(0.f, 0.f, 0.f, 0.f);

    for (int c = 0; c < np; ++c) {
        const int base = c * CHUNK;

        float4 n4[CHUNK];
        #pragma unroll
        for (int j = 0; j < CHUNK; ++j) {
            const int nb = list[base + j];
            n4[j] = embv[(size_t)nb * 32 + lane];
        }

        float p[CHUNK];
        #pragma unroll
        for (int j = 0; j < CHUNK; ++j)
            p[j] = n4[j].x * node.x + n4[j].y * node.y
                 + n4[j].z * node.z + n4[j].w * node.w;

        #pragma unroll
        for (int j = 0; j < CHUNK; ++j)
            p[j] = warp_sum(p[j]);   // independent butterfly chains interleave

        #pragma unroll
        for (int j = 0; j < CHUNK; ++j) {
            const float att = (base + j < cnt) ? p[j] * INV_ATT_SCALE : 0.0f;
            acc.x += att * n4[j].x;
            acc.y += att * n4[j].y;
            acc.z += att * n4[j].z;
            acc.w += att * n4[j].w;
        }
    }

    // ---- x = node + att_out, LayerNorm over D=128 ----
    float4 x;
    x.x = node.x + acc.x;
    x.y = node.y + acc.y;
    x.z = node.z + acc.z;
    x.w = node.w + acc.w;

    const float mu = warp_sum(x.x + x.y + x.z + x.w) * (1.0f / DDIM);

    const float dx0 = x.x - mu, dx1 = x.y - mu, dx2 = x.z - mu, dx3 = x.w - mu;
    const float var = warp_sum(dx0*dx0 + dx1*dx1 + dx2*dx2 + dx3*dx3) * (1.0f / DDIM);
    const float r = rsqrtf(var + LN_EPS);

    const float4 g = reinterpret_cast<const float4*>(gamma)[lane];
    const float4 b = reinterpret_cast<const float4*>(beta)[lane];

    float4 o;
    o.x = dx0 * r * g.x + b.x;
    o.y = dx1 * r * g.y + b.y;
    o.z = dx2 * r * g.z + b.z;
    o.w = dx3 * r * g.w + b.w;

    // streaming store: output is never re-read; don't pollute L2
    __stcs(&reinterpret_cast<float4*>(out)[(size_t)row * 32 + lane], o);
}

extern "C" void kernel_launch(void* const* d_in, const int* in_sizes, int n_in,
                              void* d_out, int out_size)
{
    const int*   node_ids      = (const int*)  d_in[0];
    const int*   neighbor_ids  = (const int*)  d_in[1];
    const int*   neighbor_mask = (const int*)  d_in[2];
    const float* emb           = (const float*)d_in[3];
    const float* gamma         = (const float*)d_in[4];
    const float* beta          = (const float*)d_in[5];
    float*       out           = (float*)d_out;

    const int blocks = NUM_ROWS / WPB;       // 1536, exact

    graph_attention_kernel<<<blocks, THREADS>>>(node_ids, neighbor_ids, neighbor_mask,
                                                emb, gamma, beta, out);
}